// round 5
// baseline (speedup 1.0000x reference)
#include <cuda_runtime.h>
#include <cuda_fp16.h>
#include <cuda_bf16.h>

#define NMAX 100000
#define EMAX 3200000
#define K_IN 116
#define K2   (K_IN / 2)      // 58 k-pairs
#define H_OUT 256
#define TILE_R 64
#define SCAN_B 256
#define XH_W 128             // padded fp16 row width (256B, aligned)

// Scratch (static device globals: allocation-free per harness rules)
__device__ int    g_deg[NMAX];
__device__ int    g_cursor[NMAX];
__device__ float  g_dinv[NMAX];
__device__ int    g_rowptr[NMAX + 1];
__device__ int    g_col[EMAX];
__device__ float  g_agg[(size_t)NMAX * K_IN];
__device__ __half g_xh[(size_t)NMAX * XH_W];
__device__ int    g_bsum[(NMAX + SCAN_B - 1) / SCAN_B];
__device__ int    g_boff[(NMAX + SCAN_B - 1) / SCAN_B];

// ---------------------------------------------------------------------------
__global__ void zero_kernel(int n) {
    int i = blockIdx.x * blockDim.x + threadIdx.x;
    if (i < n) { g_deg[i] = 0; g_cursor[i] = 0; }
}

__global__ void count_kernel(const int* __restrict__ dst, int e) {
    int i = blockIdx.x * blockDim.x + threadIdx.x;
    if (i < e) atomicAdd(&g_deg[dst[i]], 1);
}

__global__ void dinv_kernel(int n) {
    int i = blockIdx.x * blockDim.x + threadIdx.x;
    if (i < n) g_dinv[i] = rsqrtf((float)(g_deg[i] + 1));
}

// convert: g_xh[i][c] = half(dinv[i] * x[i][c]), zero-padded to 128 cols
// thread handles half-columns c4..c4+3; uint2 store = 4 halves at element
// offset c4 (BUGFIX vs R4: was c4*2, double-striding the rows).
__global__ void convert_kernel(const float* __restrict__ x, int n) {
    int i = blockIdx.x * blockDim.x + threadIdx.x;   // n*32 threads
    int node = i >> 5;
    int c4 = (i & 31) * 4;
    if (node >= n) return;
    float di = g_dinv[node];
    __half2 h0, h1;
    if (c4 < K_IN) {
        float4 v = *(const float4*)&x[(size_t)node * K_IN + c4];
        h0 = __floats2half2_rn(v.x * di, v.y * di);
        h1 = __floats2half2_rn(v.z * di, v.w * di);
    } else {
        h0 = __floats2half2_rn(0.f, 0.f);
        h1 = h0;
    }
    uint2 u;
    u.x = *(unsigned int*)&h0;
    u.y = *(unsigned int*)&h1;
    *(uint2*)&g_xh[(size_t)node * XH_W + c4] = u;
}

// --- 3-phase scan ---------------------------------------------------------
__global__ void scanA_kernel(int n) {
    __shared__ int s[SCAN_B];
    int g = blockIdx.x * SCAN_B + threadIdx.x;
    s[threadIdx.x] = (g < n) ? g_deg[g] : 0;
    __syncthreads();
    for (int off = SCAN_B / 2; off > 0; off >>= 1) {
        if (threadIdx.x < off) s[threadIdx.x] += s[threadIdx.x + off];
        __syncthreads();
    }
    if (threadIdx.x == 0) g_bsum[blockIdx.x] = s[0];
}

__global__ void scanB_kernel(int nb) {
    __shared__ int s[512];
    int tid = threadIdx.x;
    int v = (tid < nb) ? g_bsum[tid] : 0;
    s[tid] = v;
    __syncthreads();
    for (int off = 1; off < 512; off <<= 1) {
        int t = (tid >= off) ? s[tid - off] : 0;
        __syncthreads();
        s[tid] += t;
        __syncthreads();
    }
    if (tid < nb) g_boff[tid] = s[tid] - v;
}

__global__ void scanC_kernel(int n) {
    __shared__ int s[SCAN_B];
    int tid = threadIdx.x;
    int g = blockIdx.x * SCAN_B + tid;
    int d = (g < n) ? g_deg[g] : 0;
    s[tid] = d;
    __syncthreads();
    for (int off = 1; off < SCAN_B; off <<= 1) {
        int t = (tid >= off) ? s[tid - off] : 0;
        __syncthreads();
        s[tid] += t;
        __syncthreads();
    }
    int incl = s[tid];
    int base = g_boff[blockIdx.x];
    if (g < n)      g_rowptr[g] = base + incl - d;
    if (g == n - 1) g_rowptr[n] = base + incl;
}

// --- bucket fill ----------------------------------------------------------
__global__ void fill_kernel(const int* __restrict__ src,
                            const int* __restrict__ dst, int e) {
    int i = blockIdx.x * blockDim.x + threadIdx.x;
    if (i < e) {
        int d = dst[i];
        int p = g_rowptr[d] + atomicAdd(&g_cursor[d], 1);
        g_col[p] = src[i];
    }
}

// --- pull aggregation: one warp per dst node, fp16 prescaled gathers ------
// agg[dst] = dinv[dst] * ( xh[dst] + sum_{s in N(dst)} xh[s] ),  xh = dinv*x
__global__ void agg_kernel(int n) {
    int gwarp = (blockIdx.x * blockDim.x + threadIdx.x) >> 5;
    int lane  = threadIdx.x & 31;
    if (gwarp >= n) return;
    int dst = gwarp;
    float di = g_dinv[dst];
    const uint2* xr = (const uint2*)g_xh;   // row = 32 uint2 (256 B)

    float4 acc;
    {
        uint2 u = xr[(size_t)dst * 32 + lane];
        __half2 a = *(__half2*)&u.x, b2 = *(__half2*)&u.y;
        float2 f0 = __half22float2(a), f1 = __half22float2(b2);
        acc.x = f0.x; acc.y = f0.y; acc.z = f1.x; acc.w = f1.y;
    }
    int e   = g_rowptr[dst];
    int end = g_rowptr[dst + 1];
    for (; e + 4 <= end; e += 4) {
        int s0 = g_col[e], s1 = g_col[e+1], s2 = g_col[e+2], s3 = g_col[e+3];
        uint2 u0 = xr[(size_t)s0 * 32 + lane];
        uint2 u1 = xr[(size_t)s1 * 32 + lane];
        uint2 u2 = xr[(size_t)s2 * 32 + lane];
        uint2 u3 = xr[(size_t)s3 * 32 + lane];
        float2 f;
        f = __half22float2(*(__half2*)&u0.x); acc.x += f.x; acc.y += f.y;
        f = __half22float2(*(__half2*)&u0.y); acc.z += f.x; acc.w += f.y;
        f = __half22float2(*(__half2*)&u1.x); acc.x += f.x; acc.y += f.y;
        f = __half22float2(*(__half2*)&u1.y); acc.z += f.x; acc.w += f.y;
        f = __half22float2(*(__half2*)&u2.x); acc.x += f.x; acc.y += f.y;
        f = __half22float2(*(__half2*)&u2.y); acc.z += f.x; acc.w += f.y;
        f = __half22float2(*(__half2*)&u3.x); acc.x += f.x; acc.y += f.y;
        f = __half22float2(*(__half2*)&u3.y); acc.z += f.x; acc.w += f.y;
    }
    for (; e < end; e++) {
        int s = g_col[e];
        uint2 u = xr[(size_t)s * 32 + lane];
        float2 f;
        f = __half22float2(*(__half2*)&u.x); acc.x += f.x; acc.y += f.y;
        f = __half22float2(*(__half2*)&u.y); acc.z += f.x; acc.w += f.y;
    }
    acc.x *= di; acc.y *= di; acc.z *= di; acc.w *= di;
    if (lane < K_IN / 4)   // lanes 0..28 hold real cols; 29..31 are pads
        *(float4*)&g_agg[(size_t)dst * K_IN + lane * 4] = acc;
}

// --- GEMM: out = relu(agg @ W + b), persistent blocks, conflict-free LDS --
// Warp w -> rows w*8..w*8+7 of the 64-row tile. Lane l -> cols {l+32j}.
// Wp float2[K2][256]: Wp[k2][c] = {W[2k2][c], W[2k2+1][c]}. acc = f32x2 over K.
__global__ __launch_bounds__(256) void gemm_kernel(const float* __restrict__ W,
                                                   const float* __restrict__ b,
                                                   float* __restrict__ out,
                                                   int n, int ntiles) {
    extern __shared__ float sh[];
    float2* Wp = (float2*)sh;                  // K2 * 256 float2
    float*  Xs = sh + 2 * K2 * H_OUT;          // TILE_R * K_IN
    int tid = threadIdx.x;
    int wid = tid >> 5, lane = tid & 31;

    // load + k-pair-interleave W once (coalesced: c contiguous across tid)
    for (int i = tid; i < K2 * H_OUT; i += 256) {
        int k2 = i >> 8, c = i & 255;
        Wp[i] = make_float2(W[(2 * k2) * H_OUT + c], W[(2 * k2 + 1) * H_OUT + c]);
    }
    float bv[8];
    #pragma unroll
    for (int j = 0; j < 8; j++) bv[j] = b[lane + 32 * j];

    for (int t = blockIdx.x; t < ntiles; t += gridDim.x) {
        int row0 = t * TILE_R;
        int nrows = n - row0; if (nrows > TILE_R) nrows = TILE_R;
        __syncthreads();   // Xs reuse from previous tile
        {
            const float4* Ag = (const float4*)(g_agg + (size_t)row0 * K_IN);
            float4* Xs4 = (float4*)Xs;
            int tot4 = nrows * (K_IN / 4);
            for (int i = tid; i < tot4; i += 256) Xs4[i] = Ag[i];
        }
        __syncthreads();

        unsigned long long acc[8][8];
        #pragma unroll
        for (int r = 0; r < 8; r++)
            #pragma unroll
            for (int j = 0; j < 8; j++) acc[r][j] = 0ull;

        const float* Xrow = &Xs[(wid * 8) * K_IN];
        for (int k2 = 0; k2 < K2; k2++) {
            unsigned long long xp[8];
            #pragma unroll
            for (int r = 0; r < 8; r++)
                xp[r] = *(const unsigned long long*)&Xrow[r * K_IN + 2 * k2];
            #pragma unroll
            for (int j = 0; j < 8; j++) {
                unsigned long long wv =
                    *(const unsigned long long*)&Wp[k2 * H_OUT + lane + 32 * j];
                #pragma unroll
                for (int r = 0; r < 8; r++)
                    asm("fma.rn.f32x2 %0, %1, %2, %0;"
                        : "+l"(acc[r][j]) : "l"(xp[r]), "l"(wv));
            }
        }

        #pragma unroll
        for (int r = 0; r < 8; r++) {
            int row = row0 + wid * 8 + r;
            if (row < n) {
                float* orow = &out[(size_t)row * H_OUT];
                #pragma unroll
                for (int j = 0; j < 8; j++) {
                    float lo, hi;
                    asm("mov.b64 {%0,%1}, %2;" : "=f"(lo), "=f"(hi) : "l"(acc[r][j]));
                    orow[lane + 32 * j] = fmaxf(lo + hi + bv[j], 0.f);
                }
            }
        }
    }
}

// ---------------------------------------------------------------------------
extern "C" void kernel_launch(void* const* d_in, const int* in_sizes, int n_in,
                              void* d_out, int out_size) {
    const float* x  = (const float*)d_in[0];
    const int*   ei = (const int*)d_in[1];
    const float* W  = (const float*)d_in[2];
    const float* b  = (const float*)d_in[3];
    float* out = (float*)d_out;

    int n = in_sizes[0] / K_IN;     // 100000
    int e = in_sizes[1] / 2;        // 3200000
    const int* src = ei;
    const int* dst = ei + e;

    int nb_n = (n + 255) / 256;
    int nb_e = (e + 255) / 256;
    int nb_s = (n + SCAN_B - 1) / SCAN_B;

    zero_kernel<<<nb_n, 256>>>(n);
    count_kernel<<<nb_e, 256>>>(dst, e);
    dinv_kernel<<<nb_n, 256>>>(n);
    convert_kernel<<<(n * 32 + 255) / 256, 256>>>(x, n);
    scanA_kernel<<<nb_s, SCAN_B>>>(n);
    scanB_kernel<<<1, 512>>>(nb_s);
    scanC_kernel<<<nb_s, SCAN_B>>>(n);
    fill_kernel<<<nb_e, 256>>>(src, dst, e);

    int nb_agg = (n * 32 + 255) / 256;
    agg_kernel<<<nb_agg, 256>>>(n);

    int ntiles = (n + TILE_R - 1) / TILE_R;
    int smem = (2 * K2 * H_OUT + TILE_R * K_IN) * sizeof(float);  // 148480 B
    cudaFuncSetAttribute(gemm_kernel, cudaFuncAttributeMaxDynamicSharedMemorySize, smem);
    gemm_kernel<<<148, 256, smem>>>(W, b, out, n, ntiles);
}

// round 6
// speedup vs baseline: 1.4986x; 1.4986x over previous
#include <cuda_runtime.h>
#include <cuda_fp16.h>
#include <cuda_bf16.h>

#define NMAX 100000
#define EMAX 3200000
#define K_IN 116
#define KP   120            // K padded to multiple of 8 for mma
#define H_OUT 256
#define SCAN_B 256
#define XH_W 128            // padded fp16 row width (256B, aligned)
#define ASTRIDE 124         // Xs smem row stride (floats): conflict-free A frags
#define WSTRIDE 264         // Ws smem row stride (floats): conflict-free B frags
#define GEMM_ROWS 128       // rows per block

// Scratch (static device globals: allocation-free per harness rules)
__device__ int    g_deg[NMAX];
__device__ int    g_cursor[NMAX];
__device__ float  g_dinv[NMAX];
__device__ int    g_rowptr[NMAX + 1];
__device__ int    g_col[EMAX];
__device__ float  g_agg[(size_t)NMAX * K_IN];
__device__ __half g_xh[(size_t)NMAX * XH_W];
__device__ int    g_bsum[(NMAX + SCAN_B - 1) / SCAN_B];
__device__ int    g_boff[(NMAX + SCAN_B - 1) / SCAN_B];

// ---------------------------------------------------------------------------
__global__ void zero_kernel(int n) {
    int i = blockIdx.x * blockDim.x + threadIdx.x;
    if (i < n) { g_deg[i] = 0; g_cursor[i] = 0; }
}

__global__ void count_kernel(const int* __restrict__ dst, int e) {
    int i = blockIdx.x * blockDim.x + threadIdx.x;
    if (i < e) atomicAdd(&g_deg[dst[i]], 1);
}

__global__ void dinv_kernel(int n) {
    int i = blockIdx.x * blockDim.x + threadIdx.x;
    if (i < n) g_dinv[i] = rsqrtf((float)(g_deg[i] + 1));
}

// convert: g_xh[i][c] = half(dinv[i] * x[i][c]), zero-padded to 128 cols
__global__ void convert_kernel(const float* __restrict__ x, int n) {
    int i = blockIdx.x * blockDim.x + threadIdx.x;   // n*32 threads
    int node = i >> 5;
    int c4 = (i & 31) * 4;
    if (node >= n) return;
    float di = g_dinv[node];
    __half2 h0, h1;
    if (c4 < K_IN) {
        float4 v = *(const float4*)&x[(size_t)node * K_IN + c4];
        h0 = __floats2half2_rn(v.x * di, v.y * di);
        h1 = __floats2half2_rn(v.z * di, v.w * di);
    } else {
        h0 = __floats2half2_rn(0.f, 0.f);
        h1 = h0;
    }
    uint2 u;
    u.x = *(unsigned int*)&h0;
    u.y = *(unsigned int*)&h1;
    *(uint2*)&g_xh[(size_t)node * XH_W + c4] = u;
}

// --- 3-phase scan ---------------------------------------------------------
__global__ void scanA_kernel(int n) {
    __shared__ int s[SCAN_B];
    int g = blockIdx.x * SCAN_B + threadIdx.x;
    s[threadIdx.x] = (g < n) ? g_deg[g] : 0;
    __syncthreads();
    for (int off = SCAN_B / 2; off > 0; off >>= 1) {
        if (threadIdx.x < off) s[threadIdx.x] += s[threadIdx.x + off];
        __syncthreads();
    }
    if (threadIdx.x == 0) g_bsum[blockIdx.x] = s[0];
}

__global__ void scanB_kernel(int nb) {
    __shared__ int s[512];
    int tid = threadIdx.x;
    int v = (tid < nb) ? g_bsum[tid] : 0;
    s[tid] = v;
    __syncthreads();
    for (int off = 1; off < 512; off <<= 1) {
        int t = (tid >= off) ? s[tid - off] : 0;
        __syncthreads();
        s[tid] += t;
        __syncthreads();
    }
    if (tid < nb) g_boff[tid] = s[tid] - v;
}

__global__ void scanC_kernel(int n) {
    __shared__ int s[SCAN_B];
    int tid = threadIdx.x;
    int g = blockIdx.x * SCAN_B + tid;
    int d = (g < n) ? g_deg[g] : 0;
    s[tid] = d;
    __syncthreads();
    for (int off = 1; off < SCAN_B; off <<= 1) {
        int t = (tid >= off) ? s[tid - off] : 0;
        __syncthreads();
        s[tid] += t;
        __syncthreads();
    }
    int incl = s[tid];
    int base = g_boff[blockIdx.x];
    if (g < n)      g_rowptr[g] = base + incl - d;
    if (g == n - 1) g_rowptr[n] = base + incl;
}

// --- bucket fill ----------------------------------------------------------
__global__ void fill_kernel(const int* __restrict__ src,
                            const int* __restrict__ dst, int e) {
    int i = blockIdx.x * blockDim.x + threadIdx.x;
    if (i < e) {
        int d = dst[i];
        int p = g_rowptr[d] + atomicAdd(&g_cursor[d], 1);
        g_col[p] = src[i];
    }
}

// --- pull aggregation: warp/node, fp16 gathers, 4-edge HADD2 tree ---------
// agg[dst] = dinv[dst] * ( xh[dst] + sum_{s in N(dst)} xh[s] ),  xh = dinv*x
// Key: convert half->float once per 4 edges (F2F is slow-rate); the 4-edge
// partial sum happens in half2 on the full-rate fma pipe.
__global__ void agg_kernel(int n) {
    int gwarp = (blockIdx.x * blockDim.x + threadIdx.x) >> 5;
    int lane  = threadIdx.x & 31;
    if (gwarp >= n) return;
    int dst = gwarp;
    float di = g_dinv[dst];
    const uint2* xr = (const uint2*)g_xh;   // row = 32 uint2 (256 B)

    float4 acc;
    {
        uint2 u = xr[(size_t)dst * 32 + lane];
        float2 f0 = __half22float2(*(__half2*)&u.x);
        float2 f1 = __half22float2(*(__half2*)&u.y);
        acc.x = f0.x; acc.y = f0.y; acc.z = f1.x; acc.w = f1.y;
    }
    int e   = g_rowptr[dst];
    int end = g_rowptr[dst + 1];
    for (; e + 4 <= end; e += 4) {
        int s0 = g_col[e], s1 = g_col[e+1], s2 = g_col[e+2], s3 = g_col[e+3];
        uint2 u0 = xr[(size_t)s0 * 32 + lane];
        uint2 u1 = xr[(size_t)s1 * 32 + lane];
        uint2 u2 = xr[(size_t)s2 * 32 + lane];
        uint2 u3 = xr[(size_t)s3 * 32 + lane];
        __half2 ax = __hadd2(__hadd2(*(__half2*)&u0.x, *(__half2*)&u1.x),
                             __hadd2(*(__half2*)&u2.x, *(__half2*)&u3.x));
        __half2 ay = __hadd2(__hadd2(*(__half2*)&u0.y, *(__half2*)&u1.y),
                             __hadd2(*(__half2*)&u2.y, *(__half2*)&u3.y));
        float2 f0 = __half22float2(ax);
        float2 f1 = __half22float2(ay);
        acc.x += f0.x; acc.y += f0.y; acc.z += f1.x; acc.w += f1.y;
    }
    for (; e < end; e++) {
        int s = g_col[e];
        uint2 u = xr[(size_t)s * 32 + lane];
        float2 f0 = __half22float2(*(__half2*)&u.x);
        float2 f1 = __half22float2(*(__half2*)&u.y);
        acc.x += f0.x; acc.y += f0.y; acc.z += f1.x; acc.w += f1.y;
    }
    acc.x *= di; acc.y *= di; acc.z *= di; acc.w *= di;
    if (lane < K_IN / 4)   // lanes 0..28 hold real cols; 29..31 are pads
        *(float4*)&g_agg[(size_t)dst * K_IN + lane * 4] = acc;
}

// --- GEMM: out = relu(agg @ W + b) via tf32 mma.sync.m16n8k8 --------------
// Block: 256 threads = 8 warps; tile = 128 rows x 256 cols; K padded to 120.
// Ws[KP][WSTRIDE] tf32 (126.7KB), Xs[128][ASTRIDE] tf32 (63.5KB), bias 1KB.
// Warp w -> rows w*16..w*16+15; per warp 32 n-frags (8 cols each), 128 acc regs.
__device__ __forceinline__ unsigned int f2tf32(float f) {
    unsigned int r;
    asm("cvt.rna.tf32.f32 %0, %1;" : "=r"(r) : "f"(f));
    return r;
}

__global__ __launch_bounds__(256) void gemm_kernel(const float* __restrict__ W,
                                                   const float* __restrict__ b,
                                                   float* __restrict__ out, int n) {
    extern __shared__ float sh[];
    unsigned int* Ws = (unsigned int*)sh;                    // KP * WSTRIDE
    unsigned int* Xs = (unsigned int*)(sh + KP * WSTRIDE);   // 128 * ASTRIDE
    float*        bs = sh + KP * WSTRIDE + GEMM_ROWS * ASTRIDE;
    int tid = threadIdx.x;
    int wid = tid >> 5, lane = tid & 31;
    int row0 = blockIdx.x * GEMM_ROWS;

    // Ws: [k][c], zero rows 116..119
    for (int i = tid; i < KP * H_OUT; i += 256) {
        int k = i >> 8, c = i & 255;
        float v = (k < K_IN) ? W[k * H_OUT + c] : 0.f;
        Ws[k * WSTRIDE + c] = f2tf32(v);
    }
    // Xs: [r][c], zero cols 116..119 and rows beyond n
    for (int i = tid; i < GEMM_ROWS * KP; i += 256) {
        int r = i / KP, c = i % KP;
        int grow = row0 + r;
        float v = (grow < n && c < K_IN) ? g_agg[(size_t)grow * K_IN + c] : 0.f;
        Xs[r * ASTRIDE + c] = f2tf32(v);
    }
    bs[tid] = b[tid];
    __syncthreads();

    float d[32][4];
    #pragma unroll
    for (int j = 0; j < 32; j++)
        #pragma unroll
        for (int q = 0; q < 4; q++) d[j][q] = 0.f;

    int tg = lane >> 2;          // thread group 0..7
    int tr = lane & 3;           // 0..3
    const unsigned int* Xw = Xs + (wid * 16 + tg) * ASTRIDE + tr;

    for (int ks = 0; ks < KP / 8; ks++) {
        int k0 = ks * 8;
        unsigned int a0 = Xw[k0];
        unsigned int a1 = Xw[8 * ASTRIDE + k0];
        unsigned int a2 = Xw[k0 + 4];
        unsigned int a3 = Xw[8 * ASTRIDE + k0 + 4];
        const unsigned int* Wb0 = Ws + (k0 + tr) * WSTRIDE + tg;
        const unsigned int* Wb1 = Wb0 + 4 * WSTRIDE;
        #pragma unroll
        for (int j = 0; j < 32; j++) {
            unsigned int b0 = Wb0[j * 8];
            unsigned int b1 = Wb1[j * 8];
            asm("mma.sync.aligned.m16n8k8.row.col.f32.tf32.tf32.f32 "
                "{%0,%1,%2,%3}, {%4,%5,%6,%7}, {%8,%9}, {%0,%1,%2,%3};"
                : "+f"(d[j][0]), "+f"(d[j][1]), "+f"(d[j][2]), "+f"(d[j][3])
                : "r"(a0), "r"(a1), "r"(a2), "r"(a3), "r"(b0), "r"(b1));
        }
    }

    // epilogue: bias + relu, float2 stores
    int rA = row0 + wid * 16 + tg;
    int rB = rA + 8;
    #pragma unroll
    for (int j = 0; j < 32; j++) {
        int col = j * 8 + 2 * tr;
        float bx = bs[col], by = bs[col + 1];
        if (rA < n) {
            float2 o;
            o.x = fmaxf(d[j][0] + bx, 0.f);
            o.y = fmaxf(d[j][1] + by, 0.f);
            *(float2*)&out[(size_t)rA * H_OUT + col] = o;
        }
        if (rB < n) {
            float2 o;
            o.x = fmaxf(d[j][2] + bx, 0.f);
            o.y = fmaxf(d[j][3] + by, 0.f);
            *(float2*)&out[(size_t)rB * H_OUT + col] = o;
        }
    }
}

// ---------------------------------------------------------------------------
extern "C" void kernel_launch(void* const* d_in, const int* in_sizes, int n_in,
                              void* d_out, int out_size) {
    const float* x  = (const float*)d_in[0];
    const int*   ei = (const int*)d_in[1];
    const float* W  = (const float*)d_in[2];
    const float* b  = (const float*)d_in[3];
    float* out = (float*)d_out;

    int n = in_sizes[0] / K_IN;     // 100000
    int e = in_sizes[1] / 2;        // 3200000
    const int* src = ei;
    const int* dst = ei + e;

    int nb_n = (n + 255) / 256;
    int nb_e = (e + 255) / 256;
    int nb_s = (n + SCAN_B - 1) / SCAN_B;

    zero_kernel<<<nb_n, 256>>>(n);
    count_kernel<<<nb_e, 256>>>(dst, e);
    dinv_kernel<<<nb_n, 256>>>(n);
    convert_kernel<<<(n * 32 + 255) / 256, 256>>>(x, n);
    scanA_kernel<<<nb_s, SCAN_B>>>(n);
    scanB_kernel<<<1, 512>>>(nb_s);
    scanC_kernel<<<nb_s, SCAN_B>>>(n);
    fill_kernel<<<nb_e, 256>>>(src, dst, e);

    int nb_agg = (n * 32 + 255) / 256;
    agg_kernel<<<nb_agg, 256>>>(n);

    int smem = (KP * WSTRIDE + GEMM_ROWS * ASTRIDE + H_OUT) * sizeof(float); // ~191KB
    cudaFuncSetAttribute(gemm_kernel, cudaFuncAttributeMaxDynamicSharedMemorySize, smem);
    int nb_gemm = (n + GEMM_ROWS - 1) / GEMM_ROWS;   // 782
    gemm_kernel<<<nb_gemm, 256, smem>>>(W, b, out, n);
}

// round 7
// speedup vs baseline: 2.0836x; 1.3903x over previous
#include <cuda_runtime.h>
#include <cuda_fp16.h>
#include <cuda_bf16.h>

#define NMAX 100000
#define EMAX 3200000
#define K_IN 116
#define KP   120            // K padded to multiple of 8 for mma
#define H_OUT 256
#define SCAN_B 256
#define XH_W 128            // padded fp16 row width (256B, aligned)
#define ASTRIDE 124         // Xs smem row stride (uints): conflict-free A frags
#define WSTRIDE 264         // Ws smem row stride (uints): conflict-free B frags
#define GEMM_ROWS 128       // rows per tile
#define GEMM_BLOCKS 148

// Scratch (static device globals: allocation-free per harness rules)
__device__ int          g_deg[NMAX];
__device__ int          g_cursor[NMAX];
__device__ float        g_dinv[NMAX];
__device__ int          g_rowptr[NMAX + 1];
__device__ int          g_col[EMAX];
__device__ unsigned int g_aggp[(size_t)NMAX * KP];   // tf32 bits, padded rows
__device__ unsigned int g_wt[(size_t)KP * H_OUT];    // W in tf32 bits, padded
__device__ __half       g_xh[(size_t)NMAX * XH_W];
__device__ int          g_bsum[(NMAX + SCAN_B - 1) / SCAN_B];
__device__ int          g_boff[(NMAX + SCAN_B - 1) / SCAN_B];

__device__ __forceinline__ unsigned int f2tf32(float f) {
    unsigned int r;
    asm("cvt.rna.tf32.f32 %0, %1;" : "=r"(r) : "f"(f));
    return r;
}

// ---------------------------------------------------------------------------
__global__ void zero_kernel(int n) {
    int i = blockIdx.x * blockDim.x + threadIdx.x;
    if (i < n) { g_deg[i] = 0; g_cursor[i] = 0; }
}

__global__ void count_kernel(const int* __restrict__ dst, int e) {
    int i = blockIdx.x * blockDim.x + threadIdx.x;
    if (i < e) atomicAdd(&g_deg[dst[i]], 1);
}

__global__ void dinv_kernel(int n) {
    int i = blockIdx.x * blockDim.x + threadIdx.x;
    if (i < n) g_dinv[i] = rsqrtf((float)(g_deg[i] + 1));
}

// W -> tf32 bits, rows 116..119 zeroed
__global__ void wconv_kernel(const float* __restrict__ W) {
    int i = blockIdx.x * blockDim.x + threadIdx.x;
    if (i < KP * H_OUT) {
        int k = i >> 8;
        g_wt[i] = (k < K_IN) ? f2tf32(W[i]) : 0u;
    }
}

// convert: g_xh[i][c] = half(dinv[i] * x[i][c]), zero-padded to 128 cols
__global__ void convert_kernel(const float* __restrict__ x, int n) {
    int i = blockIdx.x * blockDim.x + threadIdx.x;   // n*32 threads
    int node = i >> 5;
    int c4 = (i & 31) * 4;
    if (node >= n) return;
    float di = g_dinv[node];
    __half2 h0, h1;
    if (c4 < K_IN) {
        float4 v = *(const float4*)&x[(size_t)node * K_IN + c4];
        h0 = __floats2half2_rn(v.x * di, v.y * di);
        h1 = __floats2half2_rn(v.z * di, v.w * di);
    } else {
        h0 = __floats2half2_rn(0.f, 0.f);
        h1 = h0;
    }
    uint2 u;
    u.x = *(unsigned int*)&h0;
    u.y = *(unsigned int*)&h1;
    *(uint2*)&g_xh[(size_t)node * XH_W + c4] = u;
}

// --- 3-phase scan ---------------------------------------------------------
__global__ void scanA_kernel(int n) {
    __shared__ int s[SCAN_B];
    int g = blockIdx.x * SCAN_B + threadIdx.x;
    s[threadIdx.x] = (g < n) ? g_deg[g] : 0;
    __syncthreads();
    for (int off = SCAN_B / 2; off > 0; off >>= 1) {
        if (threadIdx.x < off) s[threadIdx.x] += s[threadIdx.x + off];
        __syncthreads();
    }
    if (threadIdx.x == 0) g_bsum[blockIdx.x] = s[0];
}

__global__ void scanB_kernel(int nb) {
    __shared__ int s[512];
    int tid = threadIdx.x;
    int v = (tid < nb) ? g_bsum[tid] : 0;
    s[tid] = v;
    __syncthreads();
    for (int off = 1; off < 512; off <<= 1) {
        int t = (tid >= off) ? s[tid - off] : 0;
        __syncthreads();
        s[tid] += t;
        __syncthreads();
    }
    if (tid < nb) g_boff[tid] = s[tid] - v;
}

__global__ void scanC_kernel(int n) {
    __shared__ int s[SCAN_B];
    int tid = threadIdx.x;
    int g = blockIdx.x * SCAN_B + tid;
    int d = (g < n) ? g_deg[g] : 0;
    s[tid] = d;
    __syncthreads();
    for (int off = 1; off < SCAN_B; off <<= 1) {
        int t = (tid >= off) ? s[tid - off] : 0;
        __syncthreads();
        s[tid] += t;
        __syncthreads();
    }
    int incl = s[tid];
    int base = g_boff[blockIdx.x];
    if (g < n)      g_rowptr[g] = base + incl - d;
    if (g == n - 1) g_rowptr[n] = base + incl;
}

// --- bucket fill ----------------------------------------------------------
__global__ void fill_kernel(const int* __restrict__ src,
                            const int* __restrict__ dst, int e) {
    int i = blockIdx.x * blockDim.x + threadIdx.x;
    if (i < e) {
        int d = dst[i];
        int p = g_rowptr[d] + atomicAdd(&g_cursor[d], 1);
        g_col[p] = src[i];
    }
}

// --- pull aggregation: warp/node, fp16 gathers, HADD2 trees, 8x unroll ----
// agg[dst] = dinv[dst] * ( xh[dst] + sum_{s in N(dst)} xh[s] ),  xh = dinv*x
// Output: tf32 bits in padded rows of 120 (lanes 0..28 data, lane 29 zeros).
__global__ void agg_kernel(int n) {
    int gwarp = (blockIdx.x * blockDim.x + threadIdx.x) >> 5;
    int lane  = threadIdx.x & 31;
    if (gwarp >= n) return;
    int dst = gwarp;
    float di = g_dinv[dst];
    const uint2* xr = (const uint2*)g_xh;   // row = 32 uint2 (256 B)

    float4 acc;
    {
        uint2 u = xr[(size_t)dst * 32 + lane];
        float2 f0 = __half22float2(*(__half2*)&u.x);
        float2 f1 = __half22float2(*(__half2*)&u.y);
        acc.x = f0.x; acc.y = f0.y; acc.z = f1.x; acc.w = f1.y;
    }
    int e   = g_rowptr[dst];
    int end = g_rowptr[dst + 1];

    for (; e + 8 <= end; e += 8) {
        int s0 = g_col[e],   s1 = g_col[e+1], s2 = g_col[e+2], s3 = g_col[e+3];
        int s4 = g_col[e+4], s5 = g_col[e+5], s6 = g_col[e+6], s7 = g_col[e+7];
        uint2 u0 = xr[(size_t)s0 * 32 + lane];
        uint2 u1 = xr[(size_t)s1 * 32 + lane];
        uint2 u2 = xr[(size_t)s2 * 32 + lane];
        uint2 u3 = xr[(size_t)s3 * 32 + lane];
        uint2 u4 = xr[(size_t)s4 * 32 + lane];
        uint2 u5 = xr[(size_t)s5 * 32 + lane];
        uint2 u6 = xr[(size_t)s6 * 32 + lane];
        uint2 u7 = xr[(size_t)s7 * 32 + lane];
        __half2 ax = __hadd2(__hadd2(*(__half2*)&u0.x, *(__half2*)&u1.x),
                             __hadd2(*(__half2*)&u2.x, *(__half2*)&u3.x));
        __half2 ay = __hadd2(__hadd2(*(__half2*)&u0.y, *(__half2*)&u1.y),
                             __hadd2(*(__half2*)&u2.y, *(__half2*)&u3.y));
        __half2 bx = __hadd2(__hadd2(*(__half2*)&u4.x, *(__half2*)&u5.x),
                             __hadd2(*(__half2*)&u6.x, *(__half2*)&u7.x));
        __half2 by = __hadd2(__hadd2(*(__half2*)&u4.y, *(__half2*)&u5.y),
                             __hadd2(*(__half2*)&u6.y, *(__half2*)&u7.y));
        float2 f0 = __half22float2(ax), f1 = __half22float2(ay);
        float2 f2 = __half22float2(bx), f3 = __half22float2(by);
        acc.x += f0.x + f2.x; acc.y += f0.y + f2.y;
        acc.z += f1.x + f3.x; acc.w += f1.y + f3.y;
    }
    for (; e + 4 <= end; e += 4) {
        int s0 = g_col[e], s1 = g_col[e+1], s2 = g_col[e+2], s3 = g_col[e+3];
        uint2 u0 = xr[(size_t)s0 * 32 + lane];
        uint2 u1 = xr[(size_t)s1 * 32 + lane];
        uint2 u2 = xr[(size_t)s2 * 32 + lane];
        uint2 u3 = xr[(size_t)s3 * 32 + lane];
        __half2 ax = __hadd2(__hadd2(*(__half2*)&u0.x, *(__half2*)&u1.x),
                             __hadd2(*(__half2*)&u2.x, *(__half2*)&u3.x));
        __half2 ay = __hadd2(__hadd2(*(__half2*)&u0.y, *(__half2*)&u1.y),
                             __hadd2(*(__half2*)&u2.y, *(__half2*)&u3.y));
        float2 f0 = __half22float2(ax), f1 = __half22float2(ay);
        acc.x += f0.x; acc.y += f0.y; acc.z += f1.x; acc.w += f1.y;
    }
    for (; e < end; e++) {
        int s = g_col[e];
        uint2 u = xr[(size_t)s * 32 + lane];
        float2 f0 = __half22float2(*(__half2*)&u.x);
        float2 f1 = __half22float2(*(__half2*)&u.y);
        acc.x += f0.x; acc.y += f0.y; acc.z += f1.x; acc.w += f1.y;
    }
    if (lane < 30) {   // 30 lanes * 4 cols = 120 padded cols
        uint4 o;
        if (lane < 29) {
            o.x = f2tf32(acc.x * di); o.y = f2tf32(acc.y * di);
            o.z = f2tf32(acc.z * di); o.w = f2tf32(acc.w * di);
        } else {
            o.x = o.y = o.z = o.w = 0u;
        }
        *(uint4*)&g_aggp[(size_t)dst * KP + lane * 4] = o;
    }
}

// --- GEMM: out = relu(agg @ W + b), tf32 mma.sync, persistent blocks ------
// 148 blocks x 8 warps; tile = 128 rows x 256 cols; W copied to smem ONCE.
__global__ __launch_bounds__(256) void gemm_kernel(const float* __restrict__ b,
                                                   float* __restrict__ out,
                                                   int n, int ntiles) {
    extern __shared__ float sh[];
    unsigned int* Ws = (unsigned int*)sh;                     // KP * WSTRIDE
    unsigned int* Xs = (unsigned int*)sh + KP * WSTRIDE;      // 128 * ASTRIDE
    float*        bs = sh + KP * WSTRIDE + GEMM_ROWS * ASTRIDE;
    int tid = threadIdx.x;
    int wid = tid >> 5, lane = tid & 31;

    // W tile: straight uint4 copies (already tf32).  120 rows x 64 uint4.
    for (int i = tid; i < KP * (H_OUT / 4); i += 256) {
        int k = i >> 6, c = i & 63;
        ((uint4*)Ws)[k * (WSTRIDE / 4) + c] = ((const uint4*)g_wt)[i];
    }
    bs[tid] = b[tid];

    int tg = lane >> 2, tr = lane & 3;

    for (int t = blockIdx.x; t < ntiles; t += GEMM_BLOCKS) {
        int row0 = t * GEMM_ROWS;
        // Xs tile: straight uint4 copies of padded tf32 agg rows.
        {
            int rmax = n - row0; if (rmax > GEMM_ROWS) rmax = GEMM_ROWS;
            const uint4* Ag = (const uint4*)(g_aggp + (size_t)row0 * KP);
            int tot = rmax * (KP / 4);   // rows * 30
            for (int i = tid; i < tot; i += 256) {
                int r = i / (KP / 4), c = i % (KP / 4);
                ((uint4*)Xs)[r * (ASTRIDE / 4) + c] = Ag[i];
            }
            // zero-fill rows past n (last tile only)
            for (int i = rmax * (KP / 4) + tid; i < GEMM_ROWS * (KP / 4); i += 256) {
                int r = i / (KP / 4), c = i % (KP / 4);
                ((uint4*)Xs)[r * (ASTRIDE / 4) + c] = make_uint4(0, 0, 0, 0);
            }
        }
        __syncthreads();

        float d[32][4];
        #pragma unroll
        for (int j = 0; j < 32; j++)
            #pragma unroll
            for (int q = 0; q < 4; q++) d[j][q] = 0.f;

        const unsigned int* Xw = Xs + (wid * 16 + tg) * ASTRIDE + tr;

        for (int ks = 0; ks < KP / 8; ks++) {
            int k0 = ks * 8;
            unsigned int a0 = Xw[k0];
            unsigned int a1 = Xw[8 * ASTRIDE + k0];
            unsigned int a2 = Xw[k0 + 4];
            unsigned int a3 = Xw[8 * ASTRIDE + k0 + 4];
            const unsigned int* Wb0 = Ws + (k0 + tr) * WSTRIDE + tg;
            const unsigned int* Wb1 = Wb0 + 4 * WSTRIDE;
            #pragma unroll
            for (int j = 0; j < 32; j++) {
                unsigned int b0 = Wb0[j * 8];
                unsigned int b1 = Wb1[j * 8];
                asm("mma.sync.aligned.m16n8k8.row.col.f32.tf32.tf32.f32 "
                    "{%0,%1,%2,%3}, {%4,%5,%6,%7}, {%8,%9}, {%0,%1,%2,%3};"
                    : "+f"(d[j][0]), "+f"(d[j][1]), "+f"(d[j][2]), "+f"(d[j][3])
                    : "r"(a0), "r"(a1), "r"(a2), "r"(a3), "r"(b0), "r"(b1));
            }
        }

        int rA = row0 + wid * 16 + tg;
        int rB = rA + 8;
        #pragma unroll
        for (int j = 0; j < 32; j++) {
            int col = j * 8 + 2 * tr;
            float bx = bs[col], by = bs[col + 1];
            if (rA < n) {
                float2 o;
                o.x = fmaxf(d[j][0] + bx, 0.f);
                o.y = fmaxf(d[j][1] + by, 0.f);
                *(float2*)&out[(size_t)rA * H_OUT + col] = o;
            }
            if (rB < n) {
                float2 o;
                o.x = fmaxf(d[j][2] + bx, 0.f);
                o.y = fmaxf(d[j][3] + by, 0.f);
                *(float2*)&out[(size_t)rB * H_OUT + col] = o;
            }
        }
        __syncthreads();   // protect Xs before next tile's fill
    }
}

// ---------------------------------------------------------------------------
extern "C" void kernel_launch(void* const* d_in, const int* in_sizes, int n_in,
                              void* d_out, int out_size) {
    const float* x  = (const float*)d_in[0];
    const int*   ei = (const int*)d_in[1];
    const float* W  = (const float*)d_in[2];
    const float* b  = (const float*)d_in[3];
    float* out = (float*)d_out;

    int n = in_sizes[0] / K_IN;     // 100000
    int e = in_sizes[1] / 2;        // 3200000
    const int* src = ei;
    const int* dst = ei + e;

    int nb_n = (n + 255) / 256;
    int nb_e = (e + 255) / 256;
    int nb_s = (n + SCAN_B - 1) / SCAN_B;

    zero_kernel<<<nb_n, 256>>>(n);
    count_kernel<<<nb_e, 256>>>(dst, e);
    wconv_kernel<<<(KP * H_OUT + 255) / 256, 256>>>(W);
    dinv_kernel<<<nb_n, 256>>>(n);
    convert_kernel<<<(n * 32 + 255) / 256, 256>>>(x, n);
    scanA_kernel<<<nb_s, SCAN_B>>>(n);
    scanB_kernel<<<1, 512>>>(nb_s);
    scanC_kernel<<<nb_s, SCAN_B>>>(n);
    fill_kernel<<<nb_e, 256>>>(src, dst, e);

    int nb_agg = (n * 32 + 255) / 256;
    agg_kernel<<<nb_agg, 256>>>(n);

    int ntiles = (n + GEMM_ROWS - 1) / GEMM_ROWS;   // 782
    int smem = (KP * WSTRIDE + GEMM_ROWS * ASTRIDE + H_OUT) * sizeof(float); // ~191KB
    cudaFuncSetAttribute(gemm_kernel, cudaFuncAttributeMaxDynamicSharedMemorySize, smem);
    gemm_kernel<<<GEMM_BLOCKS, 256, smem>>>(b, out, n, ntiles);
}

// round 8
// speedup vs baseline: 2.3608x; 1.1330x over previous
#include <cuda_runtime.h>
#include <cuda_fp16.h>
#include <cuda_bf16.h>

#define NMAX 100000
#define EMAX 3200000
#define K_IN 116
#define KPH  128            // K padded to 128 for fp16 mma (k16 steps)
#define H_OUT 256
#define SCAN_B 256
#define XH_W 128            // padded fp16 row width (256B, aligned)
#define AH_STRIDE 136       // Xs smem row stride in halves (conflict-free A frags)
#define WN_STRIDE 264       // Ws smem row stride in half2/uint (conflict-free B frags)
#define GEMM_ROWS 128
#define GEMM_BLOCKS 148

// Scratch (static device globals: allocation-free per harness rules)
__device__ int          g_deg[NMAX];
__device__ int          g_cursor[NMAX];
__device__ int          g_rowptr[NMAX + 1];
__device__ int          g_col[EMAX];
__device__ __half       g_aggh[(size_t)NMAX * KPH];       // fp16 aggregate, padded
__device__ unsigned int g_whi[(KPH / 2) * H_OUT];         // W half2 k-pair interleaved
__device__ __half       g_xh[(size_t)NMAX * XH_W];
__device__ int          g_bsum[(NMAX + SCAN_B - 1) / SCAN_B];
__device__ int          g_boff[(NMAX + SCAN_B - 1) / SCAN_B];

// ---------------------------------------------------------------------------
__global__ void zero_kernel(int n) {
    int i = blockIdx.x * blockDim.x + threadIdx.x;
    if (i < n) { g_deg[i] = 0; g_cursor[i] = 0; }
}

__global__ void count_kernel(const int* __restrict__ dst, int e) {
    int i = blockIdx.x * blockDim.x + threadIdx.x;
    if (i < e) atomicAdd(&g_deg[dst[i]], 1);
}

// W -> half2 k-pair interleaved: g_whi[k2*256+n] = {W[2k2][n], W[2k2+1][n]}
__global__ void wconv_kernel(const float* __restrict__ W) {
    int i = blockIdx.x * blockDim.x + threadIdx.x;
    if (i < (KPH / 2) * H_OUT) {
        int k2 = i >> 8, nn = i & 255;
        int k0 = 2 * k2, k1 = 2 * k2 + 1;
        float v0 = (k0 < K_IN) ? W[k0 * H_OUT + nn] : 0.f;
        float v1 = (k1 < K_IN) ? W[k1 * H_OUT + nn] : 0.f;
        __half2 h = __floats2half2_rn(v0, v1);
        g_whi[i] = *(unsigned int*)&h;
    }
}

// convert: g_xh[i][c] = half(dinv[i] * x[i][c]), zero-padded to 128 cols
__global__ void convert_kernel(const float* __restrict__ x, int n) {
    int i = blockIdx.x * blockDim.x + threadIdx.x;   // n*32 threads
    int node = i >> 5;
    int c4 = (i & 31) * 4;
    if (node >= n) return;
    float di = rsqrtf((float)(g_deg[node] + 1));
    __half2 h0, h1;
    if (c4 < K_IN) {
        float4 v = *(const float4*)&x[(size_t)node * K_IN + c4];
        h0 = __floats2half2_rn(v.x * di, v.y * di);
        h1 = __floats2half2_rn(v.z * di, v.w * di);
    } else {
        h0 = __floats2half2_rn(0.f, 0.f);
        h1 = h0;
    }
    uint2 u;
    u.x = *(unsigned int*)&h0;
    u.y = *(unsigned int*)&h1;
    *(uint2*)&g_xh[(size_t)node * XH_W + c4] = u;
}

// --- 3-phase scan ---------------------------------------------------------
__global__ void scanA_kernel(int n) {
    __shared__ int s[SCAN_B];
    int g = blockIdx.x * SCAN_B + threadIdx.x;
    s[threadIdx.x] = (g < n) ? g_deg[g] : 0;
    __syncthreads();
    for (int off = SCAN_B / 2; off > 0; off >>= 1) {
        if (threadIdx.x < off) s[threadIdx.x] += s[threadIdx.x + off];
        __syncthreads();
    }
    if (threadIdx.x == 0) g_bsum[blockIdx.x] = s[0];
}

__global__ void scanB_kernel(int nb) {
    __shared__ int s[512];
    int tid = threadIdx.x;
    int v = (tid < nb) ? g_bsum[tid] : 0;
    s[tid] = v;
    __syncthreads();
    for (int off = 1; off < 512; off <<= 1) {
        int t = (tid >= off) ? s[tid - off] : 0;
        __syncthreads();
        s[tid] += t;
        __syncthreads();
    }
    if (tid < nb) g_boff[tid] = s[tid] - v;
}

__global__ void scanC_kernel(int n) {
    __shared__ int s[SCAN_B];
    int tid = threadIdx.x;
    int g = blockIdx.x * SCAN_B + tid;
    int d = (g < n) ? g_deg[g] : 0;
    s[tid] = d;
    __syncthreads();
    for (int off = 1; off < SCAN_B; off <<= 1) {
        int t = (tid >= off) ? s[tid - off] : 0;
        __syncthreads();
        s[tid] += t;
        __syncthreads();
    }
    int incl = s[tid];
    int base = g_boff[blockIdx.x];
    if (g < n)      g_rowptr[g] = base + incl - d;
    if (g == n - 1) g_rowptr[n] = base + incl;
}

// --- bucket fill ----------------------------------------------------------
__global__ void fill_kernel(const int* __restrict__ src,
                            const int* __restrict__ dst, int e) {
    int i = blockIdx.x * blockDim.x + threadIdx.x;
    if (i < e) {
        int d = dst[i];
        int p = g_rowptr[d] + atomicAdd(&g_cursor[d], 1);
        g_col[p] = src[i];
    }
}

// --- pull aggregation: warp/node, fp16 gathers, HADD2 trees, 8x unroll ----
// agg[dst] = dinv[dst] * ( xh[dst] + sum_{s in N(dst)} xh[s] ),  xh = dinv*x
// Output: fp16, padded rows of 128 (256B).
__global__ void agg_kernel(int n) {
    int gwarp = (blockIdx.x * blockDim.x + threadIdx.x) >> 5;
    int lane  = threadIdx.x & 31;
    if (gwarp >= n) return;
    int dst = gwarp;
    float di = rsqrtf((float)(g_deg[dst] + 1));
    const uint2* xr = (const uint2*)g_xh;   // row = 32 uint2 (256 B)

    float4 acc;
    {
        uint2 u = xr[(size_t)dst * 32 + lane];
        float2 f0 = __half22float2(*(__half2*)&u.x);
        float2 f1 = __half22float2(*(__half2*)&u.y);
        acc.x = f0.x; acc.y = f0.y; acc.z = f1.x; acc.w = f1.y;
    }
    int e   = g_rowptr[dst];
    int end = g_rowptr[dst + 1];

    for (; e + 8 <= end; e += 8) {
        int s0 = g_col[e],   s1 = g_col[e+1], s2 = g_col[e+2], s3 = g_col[e+3];
        int s4 = g_col[e+4], s5 = g_col[e+5], s6 = g_col[e+6], s7 = g_col[e+7];
        uint2 u0 = xr[(size_t)s0 * 32 + lane];
        uint2 u1 = xr[(size_t)s1 * 32 + lane];
        uint2 u2 = xr[(size_t)s2 * 32 + lane];
        uint2 u3 = xr[(size_t)s3 * 32 + lane];
        uint2 u4 = xr[(size_t)s4 * 32 + lane];
        uint2 u5 = xr[(size_t)s5 * 32 + lane];
        uint2 u6 = xr[(size_t)s6 * 32 + lane];
        uint2 u7 = xr[(size_t)s7 * 32 + lane];
        __half2 ax = __hadd2(__hadd2(*(__half2*)&u0.x, *(__half2*)&u1.x),
                             __hadd2(*(__half2*)&u2.x, *(__half2*)&u3.x));
        __half2 ay = __hadd2(__hadd2(*(__half2*)&u0.y, *(__half2*)&u1.y),
                             __hadd2(*(__half2*)&u2.y, *(__half2*)&u3.y));
        __half2 bx = __hadd2(__hadd2(*(__half2*)&u4.x, *(__half2*)&u5.x),
                             __hadd2(*(__half2*)&u6.x, *(__half2*)&u7.x));
        __half2 by = __hadd2(__hadd2(*(__half2*)&u4.y, *(__half2*)&u5.y),
                             __hadd2(*(__half2*)&u6.y, *(__half2*)&u7.y));
        float2 f0 = __half22float2(ax), f1 = __half22float2(ay);
        float2 f2 = __half22float2(bx), f3 = __half22float2(by);
        acc.x += f0.x + f2.x; acc.y += f0.y + f2.y;
        acc.z += f1.x + f3.x; acc.w += f1.y + f3.y;
    }
    for (; e + 4 <= end; e += 4) {
        int s0 = g_col[e], s1 = g_col[e+1], s2 = g_col[e+2], s3 = g_col[e+3];
        uint2 u0 = xr[(size_t)s0 * 32 + lane];
        uint2 u1 = xr[(size_t)s1 * 32 + lane];
        uint2 u2 = xr[(size_t)s2 * 32 + lane];
        uint2 u3 = xr[(size_t)s3 * 32 + lane];
        __half2 ax = __hadd2(__hadd2(*(__half2*)&u0.x, *(__half2*)&u1.x),
                             __hadd2(*(__half2*)&u2.x, *(__half2*)&u3.x));
        __half2 ay = __hadd2(__hadd2(*(__half2*)&u0.y, *(__half2*)&u1.y),
                             __hadd2(*(__half2*)&u2.y, *(__half2*)&u3.y));
        float2 f0 = __half22float2(ax), f1 = __half22float2(ay);
        acc.x += f0.x; acc.y += f0.y; acc.z += f1.x; acc.w += f1.y;
    }
    for (; e < end; e++) {
        int s = g_col[e];
        uint2 u = xr[(size_t)s * 32 + lane];
        float2 f0 = __half22float2(*(__half2*)&u.x);
        float2 f1 = __half22float2(*(__half2*)&u.y);
        acc.x += f0.x; acc.y += f0.y; acc.z += f1.x; acc.w += f1.y;
    }
    // store fp16 padded row (lanes 29..31 write zeros; lane 28 covers 112..115)
    uint2 o;
    if (lane < 29) {
        __half2 h0 = __floats2half2_rn(acc.x * di, acc.y * di);
        __half2 h1 = __floats2half2_rn(acc.z * di, acc.w * di);
        o.x = *(unsigned int*)&h0;
        o.y = *(unsigned int*)&h1;
    } else {
        o.x = 0u; o.y = 0u;
    }
    *(uint2*)&g_aggh[(size_t)dst * KPH + lane * 4] = o;
}

// --- GEMM: out = relu(agg @ W + b), fp16 mma.sync.m16n8k16, persistent ----
// 148 blocks x 8 warps; tile 128 rows x 256 cols; K padded to 128 (8 k-steps).
// Ws: uint (half2 k-pairs) [64][WN_STRIDE]; Xs: half [128][AH_STRIDE]; W once.
__global__ __launch_bounds__(256) void gemm_kernel(const float* __restrict__ b,
                                                   float* __restrict__ out,
                                                   int n, int ntiles) {
    extern __shared__ float sh[];
    unsigned int* Ws = (unsigned int*)sh;                         // 64 * 264
    __half*       Xs = (__half*)(Ws + (KPH / 2) * WN_STRIDE);     // 128 * 136
    float*        bs = (float*)(Xs + GEMM_ROWS * AH_STRIDE);
    int tid = threadIdx.x;
    int wid = tid >> 5, lane = tid & 31;

    // W tile once: 64 rows x 64 uint4  ->  rows of 66 uint4 (264 uints)
    for (int i = tid; i < (KPH / 2) * (H_OUT / 4); i += 256) {
        int r = i >> 6, c = i & 63;
        ((uint4*)Ws)[r * (WN_STRIDE / 4) + c] = ((const uint4*)g_whi)[i];
    }
    bs[tid] = b[tid];

    int tg = lane >> 2, tr = lane & 3;

    for (int t = blockIdx.x; t < ntiles; t += GEMM_BLOCKS) {
        int row0 = t * GEMM_ROWS;
        {
            int rmax = n - row0; if (rmax > GEMM_ROWS) rmax = GEMM_ROWS;
            const uint4* Ag = (const uint4*)(g_aggh + (size_t)row0 * KPH);
            int tot = rmax * 16;                 // 16 uint4 per 256B row
            for (int i = tid; i < tot; i += 256) {
                int r = i >> 4, c = i & 15;
                ((uint4*)Xs)[r * 17 + c] = Ag[i];   // 136 halves = 17 uint4
            }
            for (int i = rmax * 16 + tid; i < GEMM_ROWS * 16; i += 256) {
                int r = i >> 4, c = i & 15;
                ((uint4*)Xs)[r * 17 + c] = make_uint4(0, 0, 0, 0);
            }
        }
        __syncthreads();

        float d[32][4];
        #pragma unroll
        for (int j = 0; j < 32; j++)
            #pragma unroll
            for (int q = 0; q < 4; q++) d[j][q] = 0.f;

        const __half* Xw = Xs + (wid * 16 + tg) * AH_STRIDE;

        #pragma unroll
        for (int ks = 0; ks < KPH / 16; ks++) {
            int k0 = ks * 16;
            unsigned int a0 = *(const unsigned int*)&Xw[k0 + 2 * tr];
            unsigned int a1 = *(const unsigned int*)&Xw[8 * AH_STRIDE + k0 + 2 * tr];
            unsigned int a2 = *(const unsigned int*)&Xw[k0 + 2 * tr + 8];
            unsigned int a3 = *(const unsigned int*)&Xw[8 * AH_STRIDE + k0 + 2 * tr + 8];
            const unsigned int* Wb0 = Ws + (k0 / 2 + tr) * WN_STRIDE + tg;
            const unsigned int* Wb1 = Wb0 + 4 * WN_STRIDE;
            #pragma unroll
            for (int j = 0; j < 32; j++) {
                unsigned int b0 = Wb0[j * 8];
                unsigned int b1 = Wb1[j * 8];
                asm("mma.sync.aligned.m16n8k16.row.col.f32.f16.f16.f32 "
                    "{%0,%1,%2,%3}, {%4,%5,%6,%7}, {%8,%9}, {%0,%1,%2,%3};"
                    : "+f"(d[j][0]), "+f"(d[j][1]), "+f"(d[j][2]), "+f"(d[j][3])
                    : "r"(a0), "r"(a1), "r"(a2), "r"(a3), "r"(b0), "r"(b1));
            }
        }

        int rA = row0 + wid * 16 + tg;
        int rB = rA + 8;
        #pragma unroll
        for (int j = 0; j < 32; j++) {
            int col = j * 8 + 2 * tr;
            float bx = bs[col], by = bs[col + 1];
            if (rA < n) {
                float2 o;
                o.x = fmaxf(d[j][0] + bx, 0.f);
                o.y = fmaxf(d[j][1] + by, 0.f);
                *(float2*)&out[(size_t)rA * H_OUT + col] = o;
            }
            if (rB < n) {
                float2 o;
                o.x = fmaxf(d[j][2] + bx, 0.f);
                o.y = fmaxf(d[j][3] + by, 0.f);
                *(float2*)&out[(size_t)rB * H_OUT + col] = o;
            }
        }
        __syncthreads();   // protect Xs before next tile's fill
    }
}

// ---------------------------------------------------------------------------
extern "C" void kernel_launch(void* const* d_in, const int* in_sizes, int n_in,
                              void* d_out, int out_size) {
    const float* x  = (const float*)d_in[0];
    const int*   ei = (const int*)d_in[1];
    const float* W  = (const float*)d_in[2];
    const float* b  = (const float*)d_in[3];
    float* out = (float*)d_out;

    int n = in_sizes[0] / K_IN;     // 100000
    int e = in_sizes[1] / 2;        // 3200000
    const int* src = ei;
    const int* dst = ei + e;

    int nb_n = (n + 255) / 256;
    int nb_e = (e + 255) / 256;
    int nb_s = (n + SCAN_B - 1) / SCAN_B;

    zero_kernel<<<nb_n, 256>>>(n);
    count_kernel<<<nb_e, 256>>>(dst, e);
    wconv_kernel<<<((KPH / 2) * H_OUT + 255) / 256, 256>>>(W);
    convert_kernel<<<(n * 32 + 255) / 256, 256>>>(x, n);
    scanA_kernel<<<nb_s, SCAN_B>>>(n);
    scanB_kernel<<<1, 512>>>(nb_s);
    scanC_kernel<<<nb_s, SCAN_B>>>(n);
    fill_kernel<<<nb_e, 256>>>(src, dst, e);

    int nb_agg = (n * 32 + 255) / 256;
    agg_kernel<<<nb_agg, 256>>>(n);

    int ntiles = (n + GEMM_ROWS - 1) / GEMM_ROWS;   // 782
    int smem = (KPH / 2) * WN_STRIDE * 4 + GEMM_ROWS * AH_STRIDE * 2 + H_OUT * 4;
    cudaFuncSetAttribute(gemm_kernel, cudaFuncAttributeMaxDynamicSharedMemorySize, smem);
    gemm_kernel<<<GEMM_BLOCKS, 256, smem>>>(b, out, n, ntiles);
}